// round 1
// baseline (speedup 1.0000x reference)
#include <cuda_runtime.h>
#include <cstddef>

#define BATCH 256
#define SEQ   128
#define DM    1024
#define HS    1024

// Scratch for projected Q, K, V (device globals: allocation-guard-safe)
__device__ float g_Q[(size_t)BATCH * SEQ * HS];
__device__ float g_K[(size_t)BATCH * SEQ * HS];
__device__ float g_V[(size_t)BATCH * SEQ * HS];

// ---------------------------------------------------------------------------
// Projection GEMM: C[M,N] = A[M,K] * B[K,N]; M=32768, N=1024, K=1024 (fp32)
// BM=BN=128, BK=16, 256 threads, 8x8 microtile per thread.
// ---------------------------------------------------------------------------
__global__ __launch_bounds__(256) void proj_gemm(const float* __restrict__ A,
                                                 const float* __restrict__ B,
                                                 float* __restrict__ C)
{
    __shared__ float As[16][132];   // As[k][m] (transposed)
    __shared__ float Bs[16][132];   // Bs[k][n]

    const int tid = threadIdx.x;
    const int tx  = tid & 15;       // 0..15 (n dir)
    const int ty  = tid >> 4;       // 0..15 (m dir)
    const int m0  = blockIdx.y * 128;
    const int n0  = blockIdx.x * 128;

    float acc[8][8];
    #pragma unroll
    for (int i = 0; i < 8; i++)
        #pragma unroll
        for (int j = 0; j < 8; j++) acc[i][j] = 0.f;

    for (int k0 = 0; k0 < DM; k0 += 16) {
        // A tile: 128 rows x 16 cols = 512 float4 (2 per thread), store transposed
        #pragma unroll
        for (int l = 0; l < 2; l++) {
            int idx = tid + l * 256;
            int row = idx >> 2;     // 0..127
            int c4  = idx & 3;      // 0..3
            float4 a4 = *reinterpret_cast<const float4*>(
                A + (size_t)(m0 + row) * DM + k0 + c4 * 4);
            As[c4 * 4 + 0][row] = a4.x;
            As[c4 * 4 + 1][row] = a4.y;
            As[c4 * 4 + 2][row] = a4.z;
            As[c4 * 4 + 3][row] = a4.w;
        }
        // B tile: 16 rows x 128 cols = 512 float4
        #pragma unroll
        for (int l = 0; l < 2; l++) {
            int idx = tid + l * 256;
            int row = idx >> 5;     // 0..15
            int c4  = idx & 31;     // 0..31
            float4 b4 = *reinterpret_cast<const float4*>(
                B + (size_t)(k0 + row) * HS + n0 + c4 * 4);
            *reinterpret_cast<float4*>(&Bs[row][c4 * 4]) = b4;
        }
        __syncthreads();

        #pragma unroll
        for (int kk = 0; kk < 16; kk++) {
            float a[8], b[8];
            *reinterpret_cast<float4*>(a)     = *reinterpret_cast<const float4*>(&As[kk][ty * 8]);
            *reinterpret_cast<float4*>(a + 4) = *reinterpret_cast<const float4*>(&As[kk][ty * 8 + 4]);
            *reinterpret_cast<float4*>(b)     = *reinterpret_cast<const float4*>(&Bs[kk][tx * 8]);
            *reinterpret_cast<float4*>(b + 4) = *reinterpret_cast<const float4*>(&Bs[kk][tx * 8 + 4]);
            #pragma unroll
            for (int i = 0; i < 8; i++)
                #pragma unroll
                for (int j = 0; j < 8; j++)
                    acc[i][j] = fmaf(a[i], b[j], acc[i][j]);
        }
        __syncthreads();
    }

    #pragma unroll
    for (int i = 0; i < 8; i++) {
        float* crow = C + (size_t)(m0 + ty * 8 + i) * HS + n0 + tx * 8;
        *reinterpret_cast<float4*>(crow)     = make_float4(acc[i][0], acc[i][1], acc[i][2], acc[i][3]);
        *reinterpret_cast<float4*>(crow + 4) = make_float4(acc[i][4], acc[i][5], acc[i][6], acc[i][7]);
    }
}

// ---------------------------------------------------------------------------
// Attention: one block per batch. scores = Q K^T * (1/32), causal softmax,
// out = P V. S=128, H=1024. 256 threads.
// Dynamic smem: P[128][129] + two 16x132 tiles = 82944 bytes.
// ---------------------------------------------------------------------------
#define ATTN_SMEM ((128 * 129 + 2 * 16 * 132) * 4)

__global__ __launch_bounds__(256) void attn_kernel(float* __restrict__ O)
{
    extern __shared__ float sm[];
    float* P  = sm;                    // [128][129]
    float* Ts0 = sm + 128 * 129;       // [16][132]  (Qs, later Vs)
    float* Ts1 = Ts0 + 16 * 132;       // [16][132]  (Ks)

    const int tid = threadIdx.x;
    const int tx  = tid & 15;
    const int ty  = tid >> 4;
    const int b   = blockIdx.x;

    const float* Qb = g_Q + (size_t)b * SEQ * HS;
    const float* Kb = g_K + (size_t)b * SEQ * HS;
    const float* Vb = g_V + (size_t)b * SEQ * HS;

    // ---- scores = Q K^T ----
    float acc[8][8];
    #pragma unroll
    for (int i = 0; i < 8; i++)
        #pragma unroll
        for (int j = 0; j < 8; j++) acc[i][j] = 0.f;

    for (int k0 = 0; k0 < HS; k0 += 16) {
        #pragma unroll
        for (int l = 0; l < 2; l++) {
            int idx = tid + l * 256;
            int row = idx >> 2;     // 0..127
            int c4  = idx & 3;
            float4 q4 = *reinterpret_cast<const float4*>(Qb + (size_t)row * HS + k0 + c4 * 4);
            Ts0[(c4 * 4 + 0) * 132 + row] = q4.x;
            Ts0[(c4 * 4 + 1) * 132 + row] = q4.y;
            Ts0[(c4 * 4 + 2) * 132 + row] = q4.z;
            Ts0[(c4 * 4 + 3) * 132 + row] = q4.w;
            float4 k4 = *reinterpret_cast<const float4*>(Kb + (size_t)row * HS + k0 + c4 * 4);
            Ts1[(c4 * 4 + 0) * 132 + row] = k4.x;
            Ts1[(c4 * 4 + 1) * 132 + row] = k4.y;
            Ts1[(c4 * 4 + 2) * 132 + row] = k4.z;
            Ts1[(c4 * 4 + 3) * 132 + row] = k4.w;
        }
        __syncthreads();
        #pragma unroll
        for (int kk = 0; kk < 16; kk++) {
            float a[8], c[8];
            *reinterpret_cast<float4*>(a)     = *reinterpret_cast<const float4*>(&Ts0[kk * 132 + ty * 8]);
            *reinterpret_cast<float4*>(a + 4) = *reinterpret_cast<const float4*>(&Ts0[kk * 132 + ty * 8 + 4]);
            *reinterpret_cast<float4*>(c)     = *reinterpret_cast<const float4*>(&Ts1[kk * 132 + tx * 8]);
            *reinterpret_cast<float4*>(c + 4) = *reinterpret_cast<const float4*>(&Ts1[kk * 132 + tx * 8 + 4]);
            #pragma unroll
            for (int i = 0; i < 8; i++)
                #pragma unroll
                for (int j = 0; j < 8; j++)
                    acc[i][j] = fmaf(a[i], c[j], acc[i][j]);
        }
        __syncthreads();
    }

    // write scaled scores to P
    const float scale = 0.03125f;   // 1/sqrt(1024)
    #pragma unroll
    for (int i = 0; i < 8; i++)
        #pragma unroll
        for (int j = 0; j < 8; j++)
            P[(ty * 8 + i) * 129 + tx * 8 + j] = acc[i][j] * scale;
    __syncthreads();

    // ---- causal softmax, one thread per row ----
    if (tid < 128) {
        const int r = tid;
        float* row = P + r * 129;
        float m = -1e30f;
        for (int k = 0; k <= r; k++) m = fmaxf(m, row[k]);
        float s = 0.f;
        for (int k = 0; k <= r; k++) { float e = __expf(row[k] - m); row[k] = e; s += e; }
        float inv = 1.f / s;
        for (int k = 0; k <= r; k++) row[k] *= inv;
        for (int k = r + 1; k < 128; k++) row[k] = 0.f;
    }
    __syncthreads();

    // ---- out = P V ----  (8 n-tiles of 128; K=128 in 16-wide steps)
    for (int nt = 0; nt < 8; nt++) {
        const int n0 = nt * 128;
        float acc2[8][8];
        #pragma unroll
        for (int i = 0; i < 8; i++)
            #pragma unroll
            for (int j = 0; j < 8; j++) acc2[i][j] = 0.f;

        for (int kt = 0; kt < 128; kt += 16) {
            __syncthreads();
            #pragma unroll
            for (int l = 0; l < 2; l++) {
                int idx = tid + l * 256;
                int row = idx >> 5;     // 0..15
                int c4  = idx & 31;     // 0..31
                float4 v4 = *reinterpret_cast<const float4*>(
                    Vb + (size_t)(kt + row) * HS + n0 + c4 * 4);
                *reinterpret_cast<float4*>(&Ts0[row * 132 + c4 * 4]) = v4;
            }
            __syncthreads();
            #pragma unroll
            for (int kk = 0; kk < 16; kk++) {
                float a[8], v[8];
                #pragma unroll
                for (int i = 0; i < 8; i++)
                    a[i] = P[(ty * 8 + i) * 129 + kt + kk];
                *reinterpret_cast<float4*>(v)     = *reinterpret_cast<const float4*>(&Ts0[kk * 132 + tx * 8]);
                *reinterpret_cast<float4*>(v + 4) = *reinterpret_cast<const float4*>(&Ts0[kk * 132 + tx * 8 + 4]);
                #pragma unroll
                for (int i = 0; i < 8; i++)
                    #pragma unroll
                    for (int j = 0; j < 8; j++)
                        acc2[i][j] = fmaf(a[i], v[j], acc2[i][j]);
            }
        }
        #pragma unroll
        for (int i = 0; i < 8; i++) {
            float* orow = O + ((size_t)b * SEQ + ty * 8 + i) * HS + n0 + tx * 8;
            *reinterpret_cast<float4*>(orow)     = make_float4(acc2[i][0], acc2[i][1], acc2[i][2], acc2[i][3]);
            *reinterpret_cast<float4*>(orow + 4) = make_float4(acc2[i][4], acc2[i][5], acc2[i][6], acc2[i][7]);
        }
        __syncthreads();
    }
}

// ---------------------------------------------------------------------------
extern "C" void kernel_launch(void* const* d_in, const int* in_sizes, int n_in,
                              void* d_out, int out_size)
{
    const float* query = (const float*)d_in[0];
    const float* key   = (const float*)d_in[1];
    const float* value = (const float*)d_in[2];
    const float* w_q   = (const float*)d_in[3];
    const float* w_k   = (const float*)d_in[4];
    const float* w_v   = (const float*)d_in[5];
    float* out = (float*)d_out;

    float *Qp, *Kp, *Vp;
    cudaGetSymbolAddress((void**)&Qp, g_Q);
    cudaGetSymbolAddress((void**)&Kp, g_K);
    cudaGetSymbolAddress((void**)&Vp, g_V);

    dim3 grid(HS / 128, (BATCH * SEQ) / 128);   // (8, 256)
    proj_gemm<<<grid, 256>>>(query, w_q, Qp);
    proj_gemm<<<grid, 256>>>(key,   w_k, Kp);
    proj_gemm<<<grid, 256>>>(value, w_v, Vp);

    cudaFuncSetAttribute(attn_kernel, cudaFuncAttributeMaxDynamicSharedMemorySize, ATTN_SMEM);
    attn_kernel<<<BATCH, 256, ATTN_SMEM>>>(out);
}

// round 3
// speedup vs baseline: 2.3634x; 2.3634x over previous
#include <cuda_runtime.h>
#include <cstdint>
#include <cstddef>

#define BATCH 256
#define SEQ   128
#define DM    1024
#define HS    1024

// Scratch for projected Q, K, V (device globals: allocation-guard-safe)
__device__ float g_Q[(size_t)BATCH * SEQ * HS];
__device__ float g_K[(size_t)BATCH * SEQ * HS];
__device__ float g_V[(size_t)BATCH * SEQ * HS];

// ===========================================================================
// Helpers
// ===========================================================================
__device__ __forceinline__ uint32_t smem_u32(const void* p) {
    uint32_t a;
    asm("{ .reg .u64 t; cvta.to.shared.u64 t, %1; cvt.u32.u64 %0, t; }"
        : "=r"(a) : "l"(p));
    return a;
}

__device__ __forceinline__ uint32_t f2tf32(float x) {
    uint32_t y;
    asm("cvt.rna.tf32.f32 %0, %1;" : "=r"(y) : "f"(x));
    return y;
}

__device__ __forceinline__ void mma_tf32(float* d, const uint32_t* a, const uint32_t* b) {
    asm volatile(
        "mma.sync.aligned.m16n8k8.row.col.f32.tf32.tf32.f32 "
        "{%0,%1,%2,%3}, {%4,%5,%6,%7}, {%8,%9}, {%0,%1,%2,%3};"
        : "+f"(d[0]), "+f"(d[1]), "+f"(d[2]), "+f"(d[3])
        : "r"(a[0]), "r"(a[1]), "r"(a[2]), "r"(a[3]), "r"(b[0]), "r"(b[1]));
}

__device__ __forceinline__ void cp_async16(uint32_t dst_smem, const void* src) {
    asm volatile("cp.async.cg.shared.global [%0], [%1], 16;"
                 :: "r"(dst_smem), "l"(src));
}
__device__ __forceinline__ void cp_commit() {
    asm volatile("cp.async.commit_group;");
}
template <int N>
__device__ __forceinline__ void cp_wait() {
    asm volatile("cp.async.wait_group %0;" :: "n"(N));
}

// ===========================================================================
// Projection GEMM (mma.sync tf32): C[M,N] = A[M,K]*B[K,N]
// M=32768, N=1024, K=1024. CTA tile 128x128, BK=16, 3-stage cp.async pipeline.
// 8 warps; warp tile 32(m) x 64(n) = 2x8 m16n8k8 tiles.
// ===========================================================================
#define A_PITCH 20     // floats; banks (20g+tg)%32 all-distinct for frag loads
#define B_PITCH 136    // floats; banks (8tg+g)%32 all-distinct
#define A_STAGE (128 * A_PITCH)          // floats
#define B_STAGE (16 * B_PITCH)           // floats
#define STAGE_FLOATS (A_STAGE + B_STAGE)
#define NSTAGES 3
#define PROJ_SMEM_BYTES (NSTAGES * STAGE_FLOATS * 4)

__global__ __launch_bounds__(256) void proj_tc(const float* __restrict__ A,
                                               const float* __restrict__ Bw,
                                               float* __restrict__ C)
{
    extern __shared__ float sm[];
    const uint32_t smb = smem_u32(sm);

    const int tid  = threadIdx.x;
    const int wid  = tid >> 5;
    const int lane = tid & 31;
    const int g    = lane >> 2;       // 0..7
    const int tg   = lane & 3;        // 0..3
    const int wm   = wid >> 1;        // 0..3  (m block of 32)
    const int wn   = wid & 1;         // 0..1  (n block of 64)
    const int m0   = blockIdx.y * 128;
    const int n0   = blockIdx.x * 128;

    // cp.async chunk coords (2 chunks each for A and B per thread per stage)
    const int arow0 = tid >> 2,         aq0 = tid & 3;
    const int arow1 = (tid + 256) >> 2, aq1 = tid & 3;         // (tid+256)&3 == tid&3
    const int brow0 = tid >> 5,         bc0 = tid & 31;
    const int brow1 = (tid + 256) >> 5, bc1 = tid & 31;

    float acc[2][8][4];
    #pragma unroll
    for (int i = 0; i < 2; i++)
        #pragma unroll
        for (int j = 0; j < 8; j++)
            #pragma unroll
            for (int c = 0; c < 4; c++) acc[i][j][c] = 0.f;

    auto load_stage = [&](int ks, int buf) {
        const int k0 = ks * 16;
        const uint32_t sa = smb + (uint32_t)(buf * STAGE_FLOATS) * 4u;
        const uint32_t sb = sa + (uint32_t)A_STAGE * 4u;
        cp_async16(sa + (uint32_t)(arow0 * A_PITCH + aq0 * 4) * 4u,
                   A + (size_t)(m0 + arow0) * DM + k0 + aq0 * 4);
        cp_async16(sa + (uint32_t)(arow1 * A_PITCH + aq1 * 4) * 4u,
                   A + (size_t)(m0 + arow1) * DM + k0 + aq1 * 4);
        cp_async16(sb + (uint32_t)(brow0 * B_PITCH + bc0 * 4) * 4u,
                   Bw + (size_t)(k0 + brow0) * HS + n0 + bc0 * 4);
        cp_async16(sb + (uint32_t)(brow1 * B_PITCH + bc1 * 4) * 4u,
                   Bw + (size_t)(k0 + brow1) * HS + n0 + bc1 * 4);
    };

    // Prologue: stages 0, 1
    load_stage(0, 0); cp_commit();
    load_stage(1, 1); cp_commit();

    const int NK = DM / 16;   // 64
    for (int i = 0; i < NK; i++) {
        cp_wait<1>();
        __syncthreads();
        if (i + 2 < NK) load_stage(i + 2, (i + 2) % NSTAGES);
        cp_commit();

        const float* As = sm + (i % NSTAGES) * STAGE_FLOATS;
        const float* Bs = As + A_STAGE;

        #pragma unroll
        for (int kk = 0; kk < 16; kk += 8) {
            uint32_t afr[2][4];
            #pragma unroll
            for (int mt = 0; mt < 2; mt++) {
                const int m = wm * 32 + mt * 16;
                afr[mt][0] = f2tf32(As[(m + g)     * A_PITCH + kk + tg]);
                afr[mt][1] = f2tf32(As[(m + g + 8) * A_PITCH + kk + tg]);
                afr[mt][2] = f2tf32(As[(m + g)     * A_PITCH + kk + tg + 4]);
                afr[mt][3] = f2tf32(As[(m + g + 8) * A_PITCH + kk + tg + 4]);
            }
            uint32_t bfr[8][2];
            #pragma unroll
            for (int nt = 0; nt < 8; nt++) {
                const int n = wn * 64 + nt * 8;
                bfr[nt][0] = f2tf32(Bs[(kk + tg)     * B_PITCH + n + g]);
                bfr[nt][1] = f2tf32(Bs[(kk + tg + 4) * B_PITCH + n + g]);
            }
            #pragma unroll
            for (int mt = 0; mt < 2; mt++)
                #pragma unroll
                for (int nt = 0; nt < 8; nt++)
                    mma_tf32(acc[mt][nt], afr[mt], bfr[nt]);
        }
        __syncthreads();
    }

    // Epilogue: direct float2 stores (c0,c1)@(row g), (c2,c3)@(row g+8)
    #pragma unroll
    for (int mt = 0; mt < 2; mt++) {
        const int mrow = m0 + wm * 32 + mt * 16;
        #pragma unroll
        for (int nt = 0; nt < 8; nt++) {
            const int ncol = n0 + wn * 64 + nt * 8 + 2 * tg;
            *reinterpret_cast<float2*>(C + (size_t)(mrow + g) * HS + ncol) =
                make_float2(acc[mt][nt][0], acc[mt][nt][1]);
            *reinterpret_cast<float2*>(C + (size_t)(mrow + g + 8) * HS + ncol) =
                make_float2(acc[mt][nt][2], acc[mt][nt][3]);
        }
    }
}

// ===========================================================================
// Attention (fp32, unchanged): one block per batch.
// ===========================================================================
#define ATTN_SMEM ((128 * 129 + 2 * 16 * 132) * 4)

__global__ __launch_bounds__(256) void attn_kernel(float* __restrict__ O)
{
    extern __shared__ float smf[];
    float* P   = smf;
    float* Ts0 = smf + 128 * 129;
    float* Ts1 = Ts0 + 16 * 132;

    const int tid = threadIdx.x;
    const int tx  = tid & 15;
    const int ty  = tid >> 4;
    const int b   = blockIdx.x;

    const float* Qb = g_Q + (size_t)b * SEQ * HS;
    const float* Kb = g_K + (size_t)b * SEQ * HS;
    const float* Vb = g_V + (size_t)b * SEQ * HS;

    float acc[8][8];
    #pragma unroll
    for (int i = 0; i < 8; i++)
        #pragma unroll
        for (int j = 0; j < 8; j++) acc[i][j] = 0.f;

    for (int k0 = 0; k0 < HS; k0 += 16) {
        #pragma unroll
        for (int l = 0; l < 2; l++) {
            int idx = tid + l * 256;
            int row = idx >> 2;
            int c4  = idx & 3;
            float4 q4 = *reinterpret_cast<const float4*>(Qb + (size_t)row * HS + k0 + c4 * 4);
            Ts0[(c4 * 4 + 0) * 132 + row] = q4.x;
            Ts0[(c4 * 4 + 1) * 132 + row] = q4.y;
            Ts0[(c4 * 4 + 2) * 132 + row] = q4.z;
            Ts0[(c4 * 4 + 3) * 132 + row] = q4.w;
            float4 k4 = *reinterpret_cast<const float4*>(Kb + (size_t)row * HS + k0 + c4 * 4);
            Ts1[(c4 * 4 + 0) * 132 + row] = k4.x;
            Ts1[(c4 * 4 + 1) * 132 + row] = k4.y;
            Ts1[(c4 * 4 + 2) * 132 + row] = k4.z;
            Ts1[(c4 * 4 + 3) * 132 + row] = k4.w;
        }
        __syncthreads();
        #pragma unroll
        for (int kk = 0; kk < 16; kk++) {
            float a[8], c[8];
            *reinterpret_cast<float4*>(a)     = *reinterpret_cast<const float4*>(&Ts0[kk * 132 + ty * 8]);
            *reinterpret_cast<float4*>(a + 4) = *reinterpret_cast<const float4*>(&Ts0[kk * 132 + ty * 8 + 4]);
            *reinterpret_cast<float4*>(c)     = *reinterpret_cast<const float4*>(&Ts1[kk * 132 + tx * 8]);
            *reinterpret_cast<float4*>(c + 4) = *reinterpret_cast<const float4*>(&Ts1[kk * 132 + tx * 8 + 4]);
            #pragma unroll
            for (int i = 0; i < 8; i++)
                #pragma unroll
                for (int j = 0; j < 8; j++)
                    acc[i][j] = fmaf(a[i], c[j], acc[i][j]);
        }
        __syncthreads();
    }

    const float scale = 0.03125f;
    #pragma unroll
    for (int i = 0; i < 8; i++)
        #pragma unroll
        for (int j = 0; j < 8; j++)
            P[(ty * 8 + i) * 129 + tx * 8 + j] = acc[i][j] * scale;
    __syncthreads();

    if (tid < 128) {
        const int r = tid;
        float* row = P + r * 129;
        float m = -1e30f;
        for (int k = 0; k <= r; k++) m = fmaxf(m, row[k]);
        float s = 0.f;
        for (int k = 0; k <= r; k++) { float e = __expf(row[k] - m); row[k] = e; s += e; }
        float inv = 1.f / s;
        for (int k = 0; k <= r; k++) row[k] *= inv;
        for (int k = r + 1; k < 128; k++) row[k] = 0.f;
    }
    __syncthreads();

    for (int nt = 0; nt < 8; nt++) {
        const int n0 = nt * 128;
        float acc2[8][8];
        #pragma unroll
        for (int i = 0; i < 8; i++)
            #pragma unroll
            for (int j = 0; j < 8; j++) acc2[i][j] = 0.f;

        for (int kt = 0; kt < 128; kt += 16) {
            __syncthreads();
            #pragma unroll
            for (int l = 0; l < 2; l++) {
                int idx = tid + l * 256;
                int row = idx >> 5;
                int c4  = idx & 31;
                float4 v4 = *reinterpret_cast<const float4*>(
                    Vb + (size_t)(kt + row) * HS + n0 + c4 * 4);
                *reinterpret_cast<float4*>(&Ts0[row * 132 + c4 * 4]) = v4;
            }
            __syncthreads();
            #pragma unroll
            for (int kk = 0; kk < 16; kk++) {
                float a[8], v[8];
                #pragma unroll
                for (int i = 0; i < 8; i++)
                    a[i] = P[(ty * 8 + i) * 129 + kt + kk];
                *reinterpret_cast<float4*>(v)     = *reinterpret_cast<const float4*>(&Ts0[kk * 132 + tx * 8]);
                *reinterpret_cast<float4*>(v + 4) = *reinterpret_cast<const float4*>(&Ts0[kk * 132 + tx * 8 + 4]);
                #pragma unroll
                for (int i = 0; i < 8; i++)
                    #pragma unroll
                    for (int j = 0; j < 8; j++)
                        acc2[i][j] = fmaf(a[i], v[j], acc2[i][j]);
            }
        }
        #pragma unroll
        for (int i = 0; i < 8; i++) {
            float* orow = O + ((size_t)b * SEQ + ty * 8 + i) * HS + n0 + tx * 8;
            *reinterpret_cast<float4*>(orow)     = make_float4(acc2[i][0], acc2[i][1], acc2[i][2], acc2[i][3]);
            *reinterpret_cast<float4*>(orow + 4) = make_float4(acc2[i][4], acc2[i][5], acc2[i][6], acc2[i][7]);
        }
        __syncthreads();
    }
}

// ===========================================================================
extern "C" void kernel_launch(void* const* d_in, const int* in_sizes, int n_in,
                              void* d_out, int out_size)
{
    const float* query = (const float*)d_in[0];
    const float* key   = (const float*)d_in[1];
    const float* value = (const float*)d_in[2];
    const float* w_q   = (const float*)d_in[3];
    const float* w_k   = (const float*)d_in[4];
    const float* w_v   = (const float*)d_in[5];
    float* out = (float*)d_out;

    float *Qp, *Kp, *Vp;
    cudaGetSymbolAddress((void**)&Qp, g_Q);
    cudaGetSymbolAddress((void**)&Kp, g_K);
    cudaGetSymbolAddress((void**)&Vp, g_V);

    cudaFuncSetAttribute(proj_tc, cudaFuncAttributeMaxDynamicSharedMemorySize, PROJ_SMEM_BYTES);
    dim3 grid(HS / 128, (BATCH * SEQ) / 128);   // (8, 256)
    proj_tc<<<grid, 256, PROJ_SMEM_BYTES>>>(query, w_q, Qp);
    proj_tc<<<grid, 256, PROJ_SMEM_BYTES>>>(key,   w_k, Kp);
    proj_tc<<<grid, 256, PROJ_SMEM_BYTES>>>(value, w_v, Vp);

    cudaFuncSetAttribute(attn_kernel, cudaFuncAttributeMaxDynamicSharedMemorySize, ATTN_SMEM);
    attn_kernel<<<BATCH, 256, ATTN_SMEM>>>(out);
}

// round 4
// speedup vs baseline: 3.0261x; 1.2804x over previous
#include <cuda_runtime.h>
#include <cstdint>
#include <cstddef>

#define BATCH 256
#define SEQ   128
#define DM    1024
#define HS    1024

// Scratch for projected Q, K, V (device globals: allocation-guard-safe)
__device__ float g_Q[(size_t)BATCH * SEQ * HS];
__device__ float g_K[(size_t)BATCH * SEQ * HS];
__device__ float g_V[(size_t)BATCH * SEQ * HS];

// ===========================================================================
// Helpers
// ===========================================================================
__device__ __forceinline__ uint32_t smem_u32(const void* p) {
    uint32_t a;
    asm("{ .reg .u64 t; cvta.to.shared.u64 t, %1; cvt.u32.u64 %0, t; }"
        : "=r"(a) : "l"(p));
    return a;
}

__device__ __forceinline__ uint32_t f2tf32(float x) {
    uint32_t y;
    asm("cvt.rna.tf32.f32 %0, %1;" : "=r"(y) : "f"(x));
    return y;
}

__device__ __forceinline__ void mma_tf32(float* d, const uint32_t* a, const uint32_t* b) {
    asm volatile(
        "mma.sync.aligned.m16n8k8.row.col.f32.tf32.tf32.f32 "
        "{%0,%1,%2,%3}, {%4,%5,%6,%7}, {%8,%9}, {%0,%1,%2,%3};"
        : "+f"(d[0]), "+f"(d[1]), "+f"(d[2]), "+f"(d[3])
        : "r"(a[0]), "r"(a[1]), "r"(a[2]), "r"(a[3]), "r"(b[0]), "r"(b[1]));
}

__device__ __forceinline__ void cp_async16(uint32_t dst_smem, const void* src) {
    asm volatile("cp.async.cg.shared.global [%0], [%1], 16;"
                 :: "r"(dst_smem), "l"(src));
}
__device__ __forceinline__ void cp_commit() {
    asm volatile("cp.async.commit_group;");
}
template <int N>
__device__ __forceinline__ void cp_wait() {
    asm volatile("cp.async.wait_group %0;" :: "n"(N));
}

// ===========================================================================
// Projection GEMM (mma.sync tf32): C[M,N] = A[M,K]*B[K,N]
// M=32768, N=1024, K=1024. CTA tile 128x128, BK=16, 3-stage cp.async pipeline.
// 8 warps; warp tile 32(m) x 64(n). grid.z selects Q/K/V projection.
// ===========================================================================
#define A_PITCH 20
#define B_PITCH 136
#define A_STAGE (128 * A_PITCH)
#define B_STAGE (16 * B_PITCH)
#define STAGE_FLOATS (A_STAGE + B_STAGE)
#define NSTAGES 3
#define PROJ_SMEM_BYTES (NSTAGES * STAGE_FLOATS * 4)

__global__ __launch_bounds__(256) void proj_tc(const float* __restrict__ q_in,
                                               const float* __restrict__ k_in,
                                               const float* __restrict__ v_in,
                                               const float* __restrict__ w_q,
                                               const float* __restrict__ w_k,
                                               const float* __restrict__ w_v,
                                               float* __restrict__ q_out,
                                               float* __restrict__ k_out,
                                               float* __restrict__ v_out)
{
    extern __shared__ float sm[];
    const uint32_t smb = smem_u32(sm);

    const int z = blockIdx.z;
    const float* A  = (z == 0) ? q_in : (z == 1) ? k_in : v_in;
    const float* Bw = (z == 0) ? w_q  : (z == 1) ? w_k  : w_v;
    float*       C  = (z == 0) ? q_out : (z == 1) ? k_out : v_out;

    const int tid  = threadIdx.x;
    const int wid  = tid >> 5;
    const int lane = tid & 31;
    const int g    = lane >> 2;
    const int tg   = lane & 3;
    const int wm   = wid >> 1;
    const int wn   = wid & 1;
    const int m0   = blockIdx.y * 128;
    const int n0   = blockIdx.x * 128;

    const int arow0 = tid >> 2,         aq0 = tid & 3;
    const int arow1 = (tid + 256) >> 2;
    const int brow0 = tid >> 5,         bc0 = tid & 31;
    const int brow1 = (tid + 256) >> 5;

    float acc[2][8][4];
    #pragma unroll
    for (int i = 0; i < 2; i++)
        #pragma unroll
        for (int j = 0; j < 8; j++)
            #pragma unroll
            for (int c = 0; c < 4; c++) acc[i][j][c] = 0.f;

    auto load_stage = [&](int ks, int buf) {
        const int k0 = ks * 16;
        const uint32_t sa = smb + (uint32_t)(buf * STAGE_FLOATS) * 4u;
        const uint32_t sb = sa + (uint32_t)A_STAGE * 4u;
        cp_async16(sa + (uint32_t)(arow0 * A_PITCH + aq0 * 4) * 4u,
                   A + (size_t)(m0 + arow0) * DM + k0 + aq0 * 4);
        cp_async16(sa + (uint32_t)(arow1 * A_PITCH + aq0 * 4) * 4u,
                   A + (size_t)(m0 + arow1) * DM + k0 + aq0 * 4);
        cp_async16(sb + (uint32_t)(brow0 * B_PITCH + bc0 * 4) * 4u,
                   Bw + (size_t)(k0 + brow0) * HS + n0 + bc0 * 4);
        cp_async16(sb + (uint32_t)(brow1 * B_PITCH + bc0 * 4) * 4u,
                   Bw + (size_t)(k0 + brow1) * HS + n0 + bc0 * 4);
    };

    load_stage(0, 0); cp_commit();
    load_stage(1, 1); cp_commit();

    const int NK = DM / 16;
    for (int i = 0; i < NK; i++) {
        cp_wait<1>();
        __syncthreads();
        if (i + 2 < NK) load_stage(i + 2, (i + 2) % NSTAGES);
        cp_commit();

        const float* As = sm + (i % NSTAGES) * STAGE_FLOATS;
        const float* Bs = As + A_STAGE;

        #pragma unroll
        for (int kk = 0; kk < 16; kk += 8) {
            uint32_t afr[2][4];
            #pragma unroll
            for (int mt = 0; mt < 2; mt++) {
                const int m = wm * 32 + mt * 16;
                afr[mt][0] = f2tf32(As[(m + g)     * A_PITCH + kk + tg]);
                afr[mt][1] = f2tf32(As[(m + g + 8) * A_PITCH + kk + tg]);
                afr[mt][2] = f2tf32(As[(m + g)     * A_PITCH + kk + tg + 4]);
                afr[mt][3] = f2tf32(As[(m + g + 8) * A_PITCH + kk + tg + 4]);
            }
            uint32_t bfr[8][2];
            #pragma unroll
            for (int nt = 0; nt < 8; nt++) {
                const int n = wn * 64 + nt * 8;
                bfr[nt][0] = f2tf32(Bs[(kk + tg)     * B_PITCH + n + g]);
                bfr[nt][1] = f2tf32(Bs[(kk + tg + 4) * B_PITCH + n + g]);
            }
            #pragma unroll
            for (int mt = 0; mt < 2; mt++)
                #pragma unroll
                for (int nt = 0; nt < 8; nt++)
                    mma_tf32(acc[mt][nt], afr[mt], bfr[nt]);
        }
        __syncthreads();
    }

    #pragma unroll
    for (int mt = 0; mt < 2; mt++) {
        const int mrow = m0 + wm * 32 + mt * 16;
        #pragma unroll
        for (int nt = 0; nt < 8; nt++) {
            const int ncol = n0 + wn * 64 + nt * 8 + 2 * tg;
            *reinterpret_cast<float2*>(C + (size_t)(mrow + g) * HS + ncol) =
                make_float2(acc[mt][nt][0], acc[mt][nt][1]);
            *reinterpret_cast<float2*>(C + (size_t)(mrow + g + 8) * HS + ncol) =
                make_float2(acc[mt][nt][2], acc[mt][nt][3]);
        }
    }
}

// ===========================================================================
// Attention (mma.sync tf32): one CTA per batch, 256 threads (8 warps).
// Phase 1: S = Q K^T (K=1024), 2-stage cp.async, warp tile 32x64.
// Phase 2: causal softmax, warp-per-row with shfl reductions.
// Phase 3: O = P V, V streamed in [16k][128n] tiles, flattened 64-stage pipe.
// SMEM: 2 stages x (Qs+Ks 128x20) = 10240 floats, then P 128x132.
// ===========================================================================
#define SP 20                       // Q/K stage pitch
#define S_STAGE (2 * 128 * SP)      // floats per stage (Q + K)
#define P_OFF   (2 * S_STAGE)       // 10240 floats
#define P_PITCH 132
#define VP 136                      // V stage pitch
#define V_STAGE (16 * VP)           // 2176 floats
#define ATTN_SMEM ((P_OFF + 128 * P_PITCH) * 4)   // 108544 bytes

__global__ __launch_bounds__(256) void attn_tc(float* __restrict__ O)
{
    extern __shared__ float sm[];
    const uint32_t smb = smem_u32(sm);

    const int tid  = threadIdx.x;
    const int wid  = tid >> 5;
    const int lane = tid & 31;
    const int g    = lane >> 2;
    const int tg   = lane & 3;
    const int wm   = wid >> 1;
    const int wn   = wid & 1;
    const int b    = blockIdx.x;

    const float* Qb = g_Q + (size_t)b * SEQ * HS;
    const float* Kb = g_K + (size_t)b * SEQ * HS;
    const float* Vb = g_V + (size_t)b * SEQ * HS;
    float* P = sm + P_OFF;

    float acc[2][8][4];
    #pragma unroll
    for (int i = 0; i < 2; i++)
        #pragma unroll
        for (int j = 0; j < 8; j++)
            #pragma unroll
            for (int c = 0; c < 4; c++) acc[i][j][c] = 0.f;

    // ---------------- Phase 1: S = Q K^T ----------------
    const int r0 = tid >> 2, qq = tid & 3;
    const int r1 = (tid + 256) >> 2;

    auto load_s = [&](int ks, int buf) {
        const int k0 = ks * 16;
        const uint32_t sq = smb + (uint32_t)(buf * S_STAGE) * 4u;
        const uint32_t sk = sq + (uint32_t)(128 * SP) * 4u;
        cp_async16(sq + (uint32_t)(r0 * SP + qq * 4) * 4u, Qb + (size_t)r0 * HS + k0 + qq * 4);
        cp_async16(sq + (uint32_t)(r1 * SP + qq * 4) * 4u, Qb + (size_t)r1 * HS + k0 + qq * 4);
        cp_async16(sk + (uint32_t)(r0 * SP + qq * 4) * 4u, Kb + (size_t)r0 * HS + k0 + qq * 4);
        cp_async16(sk + (uint32_t)(r1 * SP + qq * 4) * 4u, Kb + (size_t)r1 * HS + k0 + qq * 4);
    };

    load_s(0, 0); cp_commit();
    for (int i = 0; i < 64; i++) {
        if (i + 1 < 64) { load_s(i + 1, (i + 1) & 1); cp_commit(); cp_wait<1>(); }
        else            { cp_wait<0>(); }
        __syncthreads();
        const float* Qs = sm + (i & 1) * S_STAGE;
        const float* Ks = Qs + 128 * SP;

        #pragma unroll
        for (int kk = 0; kk < 16; kk += 8) {
            uint32_t afr[2][4];
            #pragma unroll
            for (int mt = 0; mt < 2; mt++) {
                const int m = wm * 32 + mt * 16;
                afr[mt][0] = f2tf32(Qs[(m + g)     * SP + kk + tg]);
                afr[mt][1] = f2tf32(Qs[(m + g + 8) * SP + kk + tg]);
                afr[mt][2] = f2tf32(Qs[(m + g)     * SP + kk + tg + 4]);
                afr[mt][3] = f2tf32(Qs[(m + g + 8) * SP + kk + tg + 4]);
            }
            uint32_t bfr[8][2];
            #pragma unroll
            for (int nt = 0; nt < 8; nt++) {
                const int n = wn * 64 + nt * 8;
                bfr[nt][0] = f2tf32(Ks[(n + g) * SP + kk + tg]);
                bfr[nt][1] = f2tf32(Ks[(n + g) * SP + kk + tg + 4]);
            }
            #pragma unroll
            for (int mt = 0; mt < 2; mt++)
                #pragma unroll
                for (int nt = 0; nt < 8; nt++)
                    mma_tf32(acc[mt][nt], afr[mt], bfr[nt]);
        }
        __syncthreads();
    }

    // write scaled scores to P
    const float scale = 0.03125f;
    #pragma unroll
    for (int mt = 0; mt < 2; mt++) {
        const int mrow = wm * 32 + mt * 16;
        #pragma unroll
        for (int nt = 0; nt < 8; nt++) {
            const int ncol = wn * 64 + nt * 8 + 2 * tg;
            P[(mrow + g) * P_PITCH + ncol]     = acc[mt][nt][0] * scale;
            P[(mrow + g) * P_PITCH + ncol + 1] = acc[mt][nt][1] * scale;
            P[(mrow + g + 8) * P_PITCH + ncol]     = acc[mt][nt][2] * scale;
            P[(mrow + g + 8) * P_PITCH + ncol + 1] = acc[mt][nt][3] * scale;
        }
    }
    __syncthreads();

    // ---------------- Phase 2: causal softmax (warp per row) ----------------
    #pragma unroll 1
    for (int i = 0; i < 16; i++) {
        const int r = wid * 16 + i;
        float x[4];
        #pragma unroll
        for (int j = 0; j < 4; j++) {
            const int col = lane + 32 * j;
            x[j] = (col <= r) ? P[r * P_PITCH + col] : -1e30f;
        }
        float m = fmaxf(fmaxf(x[0], x[1]), fmaxf(x[2], x[3]));
        #pragma unroll
        for (int o = 16; o > 0; o >>= 1) m = fmaxf(m, __shfl_xor_sync(0xffffffffu, m, o));
        float e[4], s = 0.f;
        #pragma unroll
        for (int j = 0; j < 4; j++) {
            const int col = lane + 32 * j;
            e[j] = (col <= r) ? __expf(x[j] - m) : 0.f;
            s += e[j];
        }
        #pragma unroll
        for (int o = 16; o > 0; o >>= 1) s += __shfl_xor_sync(0xffffffffu, s, o);
        const float inv = 1.f / s;
        #pragma unroll
        for (int j = 0; j < 4; j++)
            P[r * P_PITCH + lane + 32 * j] = e[j] * inv;
    }
    __syncthreads();

    // ---------------- Phase 3: O = P V ----------------
    const int vr0 = tid >> 5, vc = tid & 31;
    const int vr1 = (tid + 256) >> 5;

    auto load_v = [&](int s) {
        const int nt = s >> 3, ki = s & 7;
        const uint32_t sv = smb + (uint32_t)((s & 1) * V_STAGE) * 4u;
        cp_async16(sv + (uint32_t)(vr0 * VP + vc * 4) * 4u,
                   Vb + (size_t)(ki * 16 + vr0) * HS + nt * 128 + vc * 4);
        cp_async16(sv + (uint32_t)(vr1 * VP + vc * 4) * 4u,
                   Vb + (size_t)(ki * 16 + vr1) * HS + nt * 128 + vc * 4);
    };

    load_v(0); cp_commit();
    for (int nt = 0; nt < 8; nt++) {
        #pragma unroll
        for (int i = 0; i < 2; i++)
            #pragma unroll
            for (int j = 0; j < 8; j++)
                #pragma unroll
                for (int c = 0; c < 4; c++) acc[i][j][c] = 0.f;

        for (int ki = 0; ki < 8; ki++) {
            const int s = nt * 8 + ki;
            if (s + 1 < 64) { load_v(s + 1); cp_commit(); cp_wait<1>(); }
            else            { cp_wait<0>(); }
            __syncthreads();
            const float* Vs = sm + (s & 1) * V_STAGE;

            #pragma unroll
            for (int kk = 0; kk < 16; kk += 8) {
                const int kc = ki * 16 + kk;
                uint32_t afr[2][4];
                #pragma unroll
                for (int mt = 0; mt < 2; mt++) {
                    const int m = wm * 32 + mt * 16;
                    afr[mt][0] = f2tf32(P[(m + g)     * P_PITCH + kc + tg]);
                    afr[mt][1] = f2tf32(P[(m + g + 8) * P_PITCH + kc + tg]);
                    afr[mt][2] = f2tf32(P[(m + g)     * P_PITCH + kc + tg + 4]);
                    afr[mt][3] = f2tf32(P[(m + g + 8) * P_PITCH + kc + tg + 4]);
                }
                uint32_t bfr[8][2];
                #pragma unroll
                for (int nt2 = 0; nt2 < 8; nt2++) {
                    const int n = wn * 64 + nt2 * 8;
                    bfr[nt2][0] = f2tf32(Vs[(kk + tg)     * VP + n + g]);
                    bfr[nt2][1] = f2tf32(Vs[(kk + tg + 4) * VP + n + g]);
                }
                #pragma unroll
                for (int mt = 0; mt < 2; mt++)
                    #pragma unroll
                    for (int nt2 = 0; nt2 < 8; nt2++)
                        mma_tf32(acc[mt][nt2], afr[mt], bfr[nt2]);
            }
            __syncthreads();
        }

        // epilogue for this n-tile
        #pragma unroll
        for (int mt = 0; mt < 2; mt++) {
            const int mrow = wm * 32 + mt * 16;
            #pragma unroll
            for (int nt2 = 0; nt2 < 8; nt2++) {
                const int ncol = nt * 128 + wn * 64 + nt2 * 8 + 2 * tg;
                *reinterpret_cast<float2*>(
                    O + ((size_t)b * SEQ + mrow + g) * HS + ncol) =
                    make_float2(acc[mt][nt2][0], acc[mt][nt2][1]);
                *reinterpret_cast<float2*>(
                    O + ((size_t)b * SEQ + mrow + g + 8) * HS + ncol) =
                    make_float2(acc[mt][nt2][2], acc[mt][nt2][3]);
            }
        }
    }
}

// ===========================================================================
extern "C" void kernel_launch(void* const* d_in, const int* in_sizes, int n_in,
                              void* d_out, int out_size)
{
    const float* query = (const float*)d_in[0];
    const float* key   = (const float*)d_in[1];
    const float* value = (const float*)d_in[2];
    const float* w_q   = (const float*)d_in[3];
    const float* w_k   = (const float*)d_in[4];
    const float* w_v   = (const float*)d_in[5];
    float* out = (float*)d_out;

    float *Qp, *Kp, *Vp;
    cudaGetSymbolAddress((void**)&Qp, g_Q);
    cudaGetSymbolAddress((void**)&Kp, g_K);
    cudaGetSymbolAddress((void**)&Vp, g_V);

    cudaFuncSetAttribute(proj_tc, cudaFuncAttributeMaxDynamicSharedMemorySize, PROJ_SMEM_BYTES);
    dim3 grid(HS / 128, (BATCH * SEQ) / 128, 3);   // (8, 256, 3)
    proj_tc<<<grid, 256, PROJ_SMEM_BYTES>>>(query, key, value, w_q, w_k, w_v, Qp, Kp, Vp);

    cudaFuncSetAttribute(attn_tc, cudaFuncAttributeMaxDynamicSharedMemorySize, ATTN_SMEM);
    attn_tc<<<BATCH, 256, ATTN_SMEM>>>(out);
}

// round 5
// speedup vs baseline: 4.1076x; 1.3574x over previous
#include <cuda_runtime.h>
#include <cstdint>
#include <cstddef>

#define BATCH 256
#define SEQ   128
#define DM    1024
#define HS    1024

// Scratch (device globals: allocation-guard-safe)
__device__ float g_T[(size_t)BATCH * SEQ * HS];   // x_q * M
__device__ float g_V[(size_t)BATCH * SEQ * HS];   // x_v * W_v
__device__ float g_M[(size_t)DM * DM];            // W_q * W_k^T

// ===========================================================================
// Helpers
// ===========================================================================
__device__ __forceinline__ uint32_t smem_u32(const void* p) {
    uint32_t a;
    asm("{ .reg .u64 t; cvta.to.shared.u64 t, %1; cvt.u32.u64 %0, t; }"
        : "=r"(a) : "l"(p));
    return a;
}

__device__ __forceinline__ uint32_t f2tf32(float x) {
    uint32_t y;
    asm("cvt.rna.tf32.f32 %0, %1;" : "=r"(y) : "f"(x));
    return y;
}

__device__ __forceinline__ void mma_tf32(float* d, const uint32_t* a, const uint32_t* b) {
    asm volatile(
        "mma.sync.aligned.m16n8k8.row.col.f32.tf32.tf32.f32 "
        "{%0,%1,%2,%3}, {%4,%5,%6,%7}, {%8,%9}, {%0,%1,%2,%3};"
        : "+f"(d[0]), "+f"(d[1]), "+f"(d[2]), "+f"(d[3])
        : "r"(a[0]), "r"(a[1]), "r"(a[2]), "r"(a[3]), "r"(b[0]), "r"(b[1]));
}

__device__ __forceinline__ void cp_async16(uint32_t dst_smem, const void* src) {
    asm volatile("cp.async.cg.shared.global [%0], [%1], 16;"
                 :: "r"(dst_smem), "l"(src));
}
__device__ __forceinline__ void cp_commit() {
    asm volatile("cp.async.commit_group;");
}
template <int N>
__device__ __forceinline__ void cp_wait() {
    asm volatile("cp.async.wait_group %0;" :: "n"(N));
}

// ===========================================================================
// NT GEMM for M = W_q * W_k^T : C[i,j] = sum_h A[i,h] B[j,h], 1024^3.
// CTA 128x128, 2-stage pipeline, both operands K-major at pitch 20.
// ===========================================================================
#define SP 20
#define NT_STAGE (2 * 128 * SP)          // floats per stage (A + B)
#define NT_SMEM (2 * NT_STAGE * 4)       // 81920 bytes

__global__ __launch_bounds__(256) void gemm_nt_M(const float* __restrict__ A,
                                                 const float* __restrict__ B,
                                                 float* __restrict__ C)
{
    extern __shared__ float sm[];
    const uint32_t smb = smem_u32(sm);

    const int tid  = threadIdx.x;
    const int wid  = tid >> 5;
    const int lane = tid & 31;
    const int g    = lane >> 2;
    const int tg   = lane & 3;
    const int wm   = wid >> 1;
    const int wn   = wid & 1;
    const int m0   = blockIdx.y * 128;
    const int n0   = blockIdx.x * 128;

    const int r0 = tid >> 2, qq = tid & 3;
    const int r1 = (tid + 256) >> 2;

    float acc[2][8][4];
    #pragma unroll
    for (int i = 0; i < 2; i++)
        #pragma unroll
        for (int j = 0; j < 8; j++)
            #pragma unroll
            for (int c = 0; c < 4; c++) acc[i][j][c] = 0.f;

    auto load_s = [&](int ks, int buf) {
        const int k0 = ks * 16;
        const uint32_t sa = smb + (uint32_t)(buf * NT_STAGE) * 4u;
        const uint32_t sb = sa + (uint32_t)(128 * SP) * 4u;
        cp_async16(sa + (uint32_t)(r0 * SP + qq * 4) * 4u, A + (size_t)(m0 + r0) * DM + k0 + qq * 4);
        cp_async16(sa + (uint32_t)(r1 * SP + qq * 4) * 4u, A + (size_t)(m0 + r1) * DM + k0 + qq * 4);
        cp_async16(sb + (uint32_t)(r0 * SP + qq * 4) * 4u, B + (size_t)(n0 + r0) * DM + k0 + qq * 4);
        cp_async16(sb + (uint32_t)(r1 * SP + qq * 4) * 4u, B + (size_t)(n0 + r1) * DM + k0 + qq * 4);
    };

    load_s(0, 0); cp_commit();
    for (int i = 0; i < 64; i++) {
        if (i + 1 < 64) { load_s(i + 1, (i + 1) & 1); cp_commit(); cp_wait<1>(); }
        else            { cp_wait<0>(); }
        __syncthreads();
        const float* As = sm + (i & 1) * NT_STAGE;
        const float* Bs = As + 128 * SP;

        #pragma unroll
        for (int kk = 0; kk < 16; kk += 8) {
            uint32_t afr[2][4];
            #pragma unroll
            for (int mt = 0; mt < 2; mt++) {
                const int m = wm * 32 + mt * 16;
                afr[mt][0] = f2tf32(As[(m + g)     * SP + kk + tg]);
                afr[mt][1] = f2tf32(As[(m + g + 8) * SP + kk + tg]);
                afr[mt][2] = f2tf32(As[(m + g)     * SP + kk + tg + 4]);
                afr[mt][3] = f2tf32(As[(m + g + 8) * SP + kk + tg + 4]);
            }
            uint32_t bfr[8][2];
            #pragma unroll
            for (int nt = 0; nt < 8; nt++) {
                const int n = wn * 64 + nt * 8;
                bfr[nt][0] = f2tf32(Bs[(n + g) * SP + kk + tg]);
                bfr[nt][1] = f2tf32(Bs[(n + g) * SP + kk + tg + 4]);
            }
            #pragma unroll
            for (int mt = 0; mt < 2; mt++)
                #pragma unroll
                for (int nt = 0; nt < 8; nt++)
                    mma_tf32(acc[mt][nt], afr[mt], bfr[nt]);
        }
        __syncthreads();
    }

    #pragma unroll
    for (int mt = 0; mt < 2; mt++) {
        const int mrow = m0 + wm * 32 + mt * 16;
        #pragma unroll
        for (int nt = 0; nt < 8; nt++) {
            const int ncol = n0 + wn * 64 + nt * 8 + 2 * tg;
            *reinterpret_cast<float2*>(C + (size_t)(mrow + g) * DM + ncol) =
                make_float2(acc[mt][nt][0], acc[mt][nt][1]);
            *reinterpret_cast<float2*>(C + (size_t)(mrow + g + 8) * DM + ncol) =
                make_float2(acc[mt][nt][2], acc[mt][nt][3]);
        }
    }
}

// ===========================================================================
// NN GEMM (mma.sync tf32): C = A[M,K]*B[K,N]; M=32768, N=K=1024.
// grid.z: 0 -> T = query * M_mat, 1 -> v = value * W_v.
// CTA 128x128, BK=16, 3-stage cp.async pipeline, warp tile 32x64.
// ===========================================================================
#define A_PITCH 20
#define B_PITCH 136
#define A_STAGE (128 * A_PITCH)
#define B_STAGE (16 * B_PITCH)
#define STAGE_FLOATS (A_STAGE + B_STAGE)
#define NSTAGES 3
#define PROJ_SMEM_BYTES (NSTAGES * STAGE_FLOATS * 4)

__global__ __launch_bounds__(256) void proj_tc(const float* __restrict__ q_in,
                                               const float* __restrict__ v_in,
                                               const float* __restrict__ m_mat,
                                               const float* __restrict__ w_v,
                                               float* __restrict__ t_out,
                                               float* __restrict__ v_out)
{
    extern __shared__ float sm[];
    const uint32_t smb = smem_u32(sm);

    const int z = blockIdx.z;
    const float* A  = (z == 0) ? q_in  : v_in;
    const float* Bw = (z == 0) ? m_mat : w_v;
    float*       C  = (z == 0) ? t_out : v_out;

    const int tid  = threadIdx.x;
    const int wid  = tid >> 5;
    const int lane = tid & 31;
    const int g    = lane >> 2;
    const int tg   = lane & 3;
    const int wm   = wid >> 1;
    const int wn   = wid & 1;
    const int m0   = blockIdx.y * 128;
    const int n0   = blockIdx.x * 128;

    const int arow0 = tid >> 2,         aq0 = tid & 3;
    const int arow1 = (tid + 256) >> 2;
    const int brow0 = tid >> 5,         bc0 = tid & 31;
    const int brow1 = (tid + 256) >> 5;

    float acc[2][8][4];
    #pragma unroll
    for (int i = 0; i < 2; i++)
        #pragma unroll
        for (int j = 0; j < 8; j++)
            #pragma unroll
            for (int c = 0; c < 4; c++) acc[i][j][c] = 0.f;

    auto load_stage = [&](int ks, int buf) {
        const int k0 = ks * 16;
        const uint32_t sa = smb + (uint32_t)(buf * STAGE_FLOATS) * 4u;
        const uint32_t sb = sa + (uint32_t)A_STAGE * 4u;
        cp_async16(sa + (uint32_t)(arow0 * A_PITCH + aq0 * 4) * 4u,
                   A + (size_t)(m0 + arow0) * DM + k0 + aq0 * 4);
        cp_async16(sa + (uint32_t)(arow1 * A_PITCH + aq0 * 4) * 4u,
                   A + (size_t)(m0 + arow1) * DM + k0 + aq0 * 4);
        cp_async16(sb + (uint32_t)(brow0 * B_PITCH + bc0 * 4) * 4u,
                   Bw + (size_t)(k0 + brow0) * HS + n0 + bc0 * 4);
        cp_async16(sb + (uint32_t)(brow1 * B_PITCH + bc0 * 4) * 4u,
                   Bw + (size_t)(k0 + brow1) * HS + n0 + bc0 * 4);
    };

    load_stage(0, 0); cp_commit();
    load_stage(1, 1); cp_commit();

    const int NK = DM / 16;
    for (int i = 0; i < NK; i++) {
        cp_wait<1>();
        __syncthreads();
        if (i + 2 < NK) load_stage(i + 2, (i + 2) % NSTAGES);
        cp_commit();

        const float* As = sm + (i % NSTAGES) * STAGE_FLOATS;
        const float* Bs = As + A_STAGE;

        #pragma unroll
        for (int kk = 0; kk < 16; kk += 8) {
            uint32_t afr[2][4];
            #pragma unroll
            for (int mt = 0; mt < 2; mt++) {
                const int m = wm * 32 + mt * 16;
                afr[mt][0] = f2tf32(As[(m + g)     * A_PITCH + kk + tg]);
                afr[mt][1] = f2tf32(As[(m + g + 8) * A_PITCH + kk + tg]);
                afr[mt][2] = f2tf32(As[(m + g)     * A_PITCH + kk + tg + 4]);
                afr[mt][3] = f2tf32(As[(m + g + 8) * A_PITCH + kk + tg + 4]);
            }
            uint32_t bfr[8][2];
            #pragma unroll
            for (int nt = 0; nt < 8; nt++) {
                const int n = wn * 64 + nt * 8;
                bfr[nt][0] = f2tf32(Bs[(kk + tg)     * B_PITCH + n + g]);
                bfr[nt][1] = f2tf32(Bs[(kk + tg + 4) * B_PITCH + n + g]);
            }
            #pragma unroll
            for (int mt = 0; mt < 2; mt++)
                #pragma unroll
                for (int nt = 0; nt < 8; nt++)
                    mma_tf32(acc[mt][nt], afr[mt], bfr[nt]);
        }
        __syncthreads();
    }

    #pragma unroll
    for (int mt = 0; mt < 2; mt++) {
        const int mrow = m0 + wm * 32 + mt * 16;
        #pragma unroll
        for (int nt = 0; nt < 8; nt++) {
            const int ncol = n0 + wn * 64 + nt * 8 + 2 * tg;
            *reinterpret_cast<float2*>(C + (size_t)(mrow + g) * HS + ncol) =
                make_float2(acc[mt][nt][0], acc[mt][nt][1]);
            *reinterpret_cast<float2*>(C + (size_t)(mrow + g + 8) * HS + ncol) =
                make_float2(acc[mt][nt][2], acc[mt][nt][3]);
        }
    }
}

// ===========================================================================
// Attention (mma.sync tf32): one CTA per batch, 256 threads.
// S = T * x_k^T  (raw key input as second operand), causal softmax, O = P*v.
// ===========================================================================
#define S_STAGE (2 * 128 * SP)
#define P_OFF   (2 * S_STAGE)
#define P_PITCH 132
#define VP 136
#define V_STAGE (16 * VP)
#define ATTN_SMEM ((P_OFF + 128 * P_PITCH) * 4)

__global__ __launch_bounds__(256) void attn_tc(const float* __restrict__ Kraw,
                                               float* __restrict__ O)
{
    extern __shared__ float sm[];
    const uint32_t smb = smem_u32(sm);

    const int tid  = threadIdx.x;
    const int wid  = tid >> 5;
    const int lane = tid & 31;
    const int g    = lane >> 2;
    const int tg   = lane & 3;
    const int wm   = wid >> 1;
    const int wn   = wid & 1;
    const int b    = blockIdx.x;

    const float* Qb = g_T + (size_t)b * SEQ * HS;
    const float* Kb = Kraw + (size_t)b * SEQ * DM;
    const float* Vb = g_V + (size_t)b * SEQ * HS;
    float* P = sm + P_OFF;

    float acc[2][8][4];
    #pragma unroll
    for (int i = 0; i < 2; i++)
        #pragma unroll
        for (int j = 0; j < 8; j++)
            #pragma unroll
            for (int c = 0; c < 4; c++) acc[i][j][c] = 0.f;

    // ---------------- Phase 1: S = T K^T ----------------
    const int r0 = tid >> 2, qq = tid & 3;
    const int r1 = (tid + 256) >> 2;

    auto load_s = [&](int ks, int buf) {
        const int k0 = ks * 16;
        const uint32_t sq = smb + (uint32_t)(buf * S_STAGE) * 4u;
        const uint32_t sk = sq + (uint32_t)(128 * SP) * 4u;
        cp_async16(sq + (uint32_t)(r0 * SP + qq * 4) * 4u, Qb + (size_t)r0 * HS + k0 + qq * 4);
        cp_async16(sq + (uint32_t)(r1 * SP + qq * 4) * 4u, Qb + (size_t)r1 * HS + k0 + qq * 4);
        cp_async16(sk + (uint32_t)(r0 * SP + qq * 4) * 4u, Kb + (size_t)r0 * DM + k0 + qq * 4);
        cp_async16(sk + (uint32_t)(r1 * SP + qq * 4) * 4u, Kb + (size_t)r1 * DM + k0 + qq * 4);
    };

    load_s(0, 0); cp_commit();
    for (int i = 0; i < 64; i++) {
        if (i + 1 < 64) { load_s(i + 1, (i + 1) & 1); cp_commit(); cp_wait<1>(); }
        else            { cp_wait<0>(); }
        __syncthreads();
        const float* Qs = sm + (i & 1) * S_STAGE;
        const float* Ks = Qs + 128 * SP;

        #pragma unroll
        for (int kk = 0; kk < 16; kk += 8) {
            uint32_t afr[2][4];
            #pragma unroll
            for (int mt = 0; mt < 2; mt++) {
                const int m = wm * 32 + mt * 16;
                afr[mt][0] = f2tf32(Qs[(m + g)     * SP + kk + tg]);
                afr[mt][1] = f2tf32(Qs[(m + g + 8) * SP + kk + tg]);
                afr[mt][2] = f2tf32(Qs[(m + g)     * SP + kk + tg + 4]);
                afr[mt][3] = f2tf32(Qs[(m + g + 8) * SP + kk + tg + 4]);
            }
            uint32_t bfr[8][2];
            #pragma unroll
            for (int nt = 0; nt < 8; nt++) {
                const int n = wn * 64 + nt * 8;
                bfr[nt][0] = f2tf32(Ks[(n + g) * SP + kk + tg]);
                bfr[nt][1] = f2tf32(Ks[(n + g) * SP + kk + tg + 4]);
            }
            #pragma unroll
            for (int mt = 0; mt < 2; mt++)
                #pragma unroll
                for (int nt = 0; nt < 8; nt++)
                    mma_tf32(acc[mt][nt], afr[mt], bfr[nt]);
        }
        __syncthreads();
    }

    const float scale = 0.03125f;
    #pragma unroll
    for (int mt = 0; mt < 2; mt++) {
        const int mrow = wm * 32 + mt * 16;
        #pragma unroll
        for (int nt = 0; nt < 8; nt++) {
            const int ncol = wn * 64 + nt * 8 + 2 * tg;
            P[(mrow + g) * P_PITCH + ncol]     = acc[mt][nt][0] * scale;
            P[(mrow + g) * P_PITCH + ncol + 1] = acc[mt][nt][1] * scale;
            P[(mrow + g + 8) * P_PITCH + ncol]     = acc[mt][nt][2] * scale;
            P[(mrow + g + 8) * P_PITCH + ncol + 1] = acc[mt][nt][3] * scale;
        }
    }
    __syncthreads();

    // ---------------- Phase 2: causal softmax (warp per row) ----------------
    #pragma unroll 1
    for (int i = 0; i < 16; i++) {
        const int r = wid * 16 + i;
        float x[4];
        #pragma unroll
        for (int j = 0; j < 4; j++) {
            const int col = lane + 32 * j;
            x[j] = (col <= r) ? P[r * P_PITCH + col] : -1e30f;
        }
        float m = fmaxf(fmaxf(x[0], x[1]), fmaxf(x[2], x[3]));
        #pragma unroll
        for (int o = 16; o > 0; o >>= 1) m = fmaxf(m, __shfl_xor_sync(0xffffffffu, m, o));
        float e[4], s = 0.f;
        #pragma unroll
        for (int j = 0; j < 4; j++) {
            const int col = lane + 32 * j;
            e[j] = (col <= r) ? __expf(x[j] - m) : 0.f;
            s += e[j];
        }
        #pragma unroll
        for (int o = 16; o > 0; o >>= 1) s += __shfl_xor_sync(0xffffffffu, s, o);
        const float inv = 1.f / s;
        #pragma unroll
        for (int j = 0; j < 4; j++)
            P[r * P_PITCH + lane + 32 * j] = e[j] * inv;
    }
    __syncthreads();

    // ---------------- Phase 3: O = P V ----------------
    const int vr0 = tid >> 5, vc = tid & 31;
    const int vr1 = (tid + 256) >> 5;

    auto load_v = [&](int s) {
        const int nt = s >> 3, ki = s & 7;
        const uint32_t sv = smb + (uint32_t)((s & 1) * V_STAGE) * 4u;
        cp_async16(sv + (uint32_t)(vr0 * VP + vc * 4) * 4u,
                   Vb + (size_t)(ki * 16 + vr0) * HS + nt * 128 + vc * 4);
        cp_async16(sv + (uint32_t)(vr1 * VP + vc * 4) * 4u,
                   Vb + (size_t)(ki * 16 + vr1) * HS + nt * 128 + vc * 4);
    };

    load_v(0); cp_commit();
    for (int nt = 0; nt < 8; nt++) {
        #pragma unroll
        for (int i = 0; i < 2; i++)
            #pragma unroll
            for (int j = 0; j < 8; j++)
                #pragma unroll
                for (int c = 0; c < 4; c++) acc[i][j][c] = 0.f;

        for (int ki = 0; ki < 8; ki++) {
            const int s = nt * 8 + ki;
            if (s + 1 < 64) { load_v(s + 1); cp_commit(); cp_wait<1>(); }
            else            { cp_wait<0>(); }
            __syncthreads();
            const float* Vs = sm + (s & 1) * V_STAGE;

            #pragma unroll
            for (int kk = 0; kk < 16; kk += 8) {
                const int kc = ki * 16 + kk;
                uint32_t afr[2][4];
                #pragma unroll
                for (int mt = 0; mt < 2; mt++) {
                    const int m = wm * 32 + mt * 16;
                    afr[mt][0] = f2tf32(P[(m + g)     * P_PITCH + kc + tg]);
                    afr[mt][1] = f2tf32(P[(m + g + 8) * P_PITCH + kc + tg]);
                    afr[mt][2] = f2tf32(P[(m + g)     * P_PITCH + kc + tg + 4]);
                    afr[mt][3] = f2tf32(P[(m + g + 8) * P_PITCH + kc + tg + 4]);
                }
                uint32_t bfr[8][2];
                #pragma unroll
                for (int nt2 = 0; nt2 < 8; nt2++) {
                    const int n = wn * 64 + nt2 * 8;
                    bfr[nt2][0] = f2tf32(Vs[(kk + tg)     * VP + n + g]);
                    bfr[nt2][1] = f2tf32(Vs[(kk + tg + 4) * VP + n + g]);
                }
                #pragma unroll
                for (int mt = 0; mt < 2; mt++)
                    #pragma unroll
                    for (int nt2 = 0; nt2 < 8; nt2++)
                        mma_tf32(acc[mt][nt2], afr[mt], bfr[nt2]);
            }
            __syncthreads();
        }

        #pragma unroll
        for (int mt = 0; mt < 2; mt++) {
            const int mrow = wm * 32 + mt * 16;
            #pragma unroll
            for (int nt2 = 0; nt2 < 8; nt2++) {
                const int ncol = nt * 128 + wn * 64 + nt2 * 8 + 2 * tg;
                *reinterpret_cast<float2*>(
                    O + ((size_t)b * SEQ + mrow + g) * HS + ncol) =
                    make_float2(acc[mt][nt2][0], acc[mt][nt2][1]);
                *reinterpret_cast<float2*>(
                    O + ((size_t)b * SEQ + mrow + g + 8) * HS + ncol) =
                    make_float2(acc[mt][nt2][2], acc[mt][nt2][3]);
            }
        }
    }
}

// ===========================================================================
extern "C" void kernel_launch(void* const* d_in, const int* in_sizes, int n_in,
                              void* d_out, int out_size)
{
    const float* query = (const float*)d_in[0];
    const float* key   = (const float*)d_in[1];
    const float* value = (const float*)d_in[2];
    const float* w_q   = (const float*)d_in[3];
    const float* w_k   = (const float*)d_in[4];
    const float* w_v   = (const float*)d_in[5];
    float* out = (float*)d_out;

    float *Tp, *Vp, *Mp;
    cudaGetSymbolAddress((void**)&Tp, g_T);
    cudaGetSymbolAddress((void**)&Vp, g_V);
    cudaGetSymbolAddress((void**)&Mp, g_M);

    // M = W_q * W_k^T
    cudaFuncSetAttribute(gemm_nt_M, cudaFuncAttributeMaxDynamicSharedMemorySize, NT_SMEM);
    gemm_nt_M<<<dim3(8, 8), 256, NT_SMEM>>>(w_q, w_k, Mp);

    // T = query * M ; v = value * W_v
    cudaFuncSetAttribute(proj_tc, cudaFuncAttributeMaxDynamicSharedMemorySize, PROJ_SMEM_BYTES);
    dim3 grid(HS / 128, (BATCH * SEQ) / 128, 2);
    proj_tc<<<grid, 256, PROJ_SMEM_BYTES>>>(query, value, Mp, w_v, Tp, Vp);

    // attention with raw key as second operand
    cudaFuncSetAttribute(attn_tc, cudaFuncAttributeMaxDynamicSharedMemorySize, ATTN_SMEM);
    attn_tc<<<BATCH, 256, ATTN_SMEM>>>(key, out);
}